// round 1
// baseline (speedup 1.0000x reference)
#include <cuda_runtime.h>
#include <cuda_bf16.h>
#include <stdint.h>

#define N_TOKENS_TOTAL 16384
#define D_PROJ 1024
#define EMB_SCALE 32.0f

// ---------------- scratch (no allocations allowed) ----------------
__device__ int g_cnt[4];
__device__ int g_tok[4][N_TOKENS_TOTAL];   // original flat token position
__device__ int g_loc[4][N_TOKENS_TOTAL];   // local embedding row within cluster

// ---------------- helpers ----------------
__device__ __forceinline__ unsigned long long fma2(unsigned long long a,
                                                   unsigned long long b,
                                                   unsigned long long c) {
    unsigned long long d;
    asm("fma.rn.f32x2 %0, %1, %2, %3;" : "=l"(d) : "l"(a), "l"(b), "l"(c));
    return d;
}
__device__ __forceinline__ unsigned long long pack2(float x, float y) {
    unsigned long long r;
    asm("mov.b64 %0, {%1, %2};" : "=l"(r) : "f"(x), "f"(y));
    return r;
}

// ---------------- kernel 1: zero counters ----------------
__global__ void zero_kernel() {
    if (threadIdx.x < 4) g_cnt[threadIdx.x] = 0;
}

// ---------------- kernel 2: bucket tokens by cluster ----------------
__global__ void bucket_kernel(const int* __restrict__ inp, int n) {
    int t = blockIdx.x * blockDim.x + threadIdx.x;
    if (t >= n) return;
    int v = inp[t];
    int c, l;
    if (v < 20000)       { c = 0; l = 0; }
    else if (v < 40000)  { c = 1; l = 20000; }
    else if (v < 200000) { c = 2; l = 40000; }
    else                 { c = 3; l = 200000; }
    int p = atomicAdd(&g_cnt[c], 1);
    g_tok[c][p] = t;
    g_loc[c][p] = v - l;
}

// ---------------- kernel 3: gathered GEMM + scatter ----------------
// out[tok[r], p] = EMB_SCALE * sum_d emb[loc[r], d] * proj[p, d]
// Tile: BM=64 tokens x BN=64 proj rows, BK=16, 256 threads, 4x4 per thread.
template <int K>
__global__ __launch_bounds__(256, 4) void gemm_kernel(
    const float* __restrict__ emb,
    const float* __restrict__ proj,
    float* __restrict__ out,
    int cluster)
{
    constexpr int BM = 64, BN = 64, BK = 16;
    __shared__ float As[BK][BM];   // transposed: [k][m]
    __shared__ float Bs[BK][BN];   // transposed: [k][n]

    const int cnt = g_cnt[cluster];
    const int m0 = blockIdx.y * BM;
    if (m0 >= cnt) return;
    const int n0 = blockIdx.x * BN;

    const int t  = threadIdx.x;          // 0..255
    const int tx = t & 15;               // 16 col groups of 4
    const int ty = t >> 4;               // 16 row groups of 4
    const int lrow = t >> 2;             // 0..63 : row loaded by this thread
    const int kg   = t & 3;              // 0..3  : 4-float group within BK

    const bool rvalid = (m0 + lrow) < cnt;
    int gl = 0;
    if (rvalid) gl = g_loc[cluster][m0 + lrow];

    const float* aptr = emb  + (size_t)gl * K + kg * 4;
    const float* bptr = proj + (size_t)(n0 + lrow) * K + kg * 4;

    unsigned long long acc2[4][2];
#pragma unroll
    for (int i = 0; i < 4; i++) { acc2[i][0] = 0ull; acc2[i][1] = 0ull; }

    // prefetch first tile
    float4 av = rvalid ? *reinterpret_cast<const float4*>(aptr)
                       : make_float4(0.f, 0.f, 0.f, 0.f);
    float4 bv = *reinterpret_cast<const float4*>(bptr);

    for (int k0 = 0; k0 < K; k0 += BK) {
        __syncthreads();   // previous compute done before overwriting smem
        As[kg * 4 + 0][lrow] = av.x;
        As[kg * 4 + 1][lrow] = av.y;
        As[kg * 4 + 2][lrow] = av.z;
        As[kg * 4 + 3][lrow] = av.w;
        Bs[kg * 4 + 0][lrow] = bv.x;
        Bs[kg * 4 + 1][lrow] = bv.y;
        Bs[kg * 4 + 2][lrow] = bv.z;
        Bs[kg * 4 + 3][lrow] = bv.w;
        __syncthreads();

        // prefetch next tile (overlaps with compute below)
        if (k0 + BK < K) {
            av = rvalid ? *reinterpret_cast<const float4*>(aptr + k0 + BK)
                        : make_float4(0.f, 0.f, 0.f, 0.f);
            bv = *reinterpret_cast<const float4*>(bptr + k0 + BK);
        }

#pragma unroll
        for (int kk = 0; kk < BK; kk++) {
            const ulonglong2 b2 =
                *reinterpret_cast<const ulonglong2*>(&Bs[kk][tx * 4]);
            const float4 a =
                *reinterpret_cast<const float4*>(&As[kk][ty * 4]);
            unsigned long long aa;
            aa = pack2(a.x, a.x);
            acc2[0][0] = fma2(aa, b2.x, acc2[0][0]);
            acc2[0][1] = fma2(aa, b2.y, acc2[0][1]);
            aa = pack2(a.y, a.y);
            acc2[1][0] = fma2(aa, b2.x, acc2[1][0]);
            acc2[1][1] = fma2(aa, b2.y, acc2[1][1]);
            aa = pack2(a.z, a.z);
            acc2[2][0] = fma2(aa, b2.x, acc2[2][0]);
            acc2[2][1] = fma2(aa, b2.y, acc2[2][1]);
            aa = pack2(a.w, a.w);
            acc2[3][0] = fma2(aa, b2.x, acc2[3][0]);
            acc2[3][1] = fma2(aa, b2.y, acc2[3][1]);
        }
    }

    // scatter-store with scale
#pragma unroll
    for (int i = 0; i < 4; i++) {
        int r = m0 + ty * 4 + i;
        if (r < cnt) {
            int row = g_tok[cluster][r];
            float2 p0 = *reinterpret_cast<float2*>(&acc2[i][0]);
            float2 p1 = *reinterpret_cast<float2*>(&acc2[i][1]);
            float4 v = make_float4(p0.x * EMB_SCALE, p0.y * EMB_SCALE,
                                   p1.x * EMB_SCALE, p1.y * EMB_SCALE);
            *reinterpret_cast<float4*>(out + (size_t)row * D_PROJ + n0 + tx * 4) = v;
        }
    }
}

// ---------------- launch ----------------
extern "C" void kernel_launch(void* const* d_in, const int* in_sizes, int n_in,
                              void* d_out, int out_size) {
    const int* inp = (const int*)d_in[0];
    const float* emb[4];
    const float* proj[4];

    // Input layout detection: interleaved (inp, emb0, proj0, emb1, proj1, ...)
    // vs grouped (inp, emb0..emb3, proj0..proj3).
    // interleaved: in_sizes[2] == 1024*1024 (proj0); grouped: in_sizes[2] == 20000*256 (emb1)
    if (n_in >= 9 && in_sizes[2] == 1024 * 1024) {
        for (int i = 0; i < 4; i++) {
            emb[i]  = (const float*)d_in[1 + 2 * i];
            proj[i] = (const float*)d_in[2 + 2 * i];
        }
    } else {
        for (int i = 0; i < 4; i++) {
            emb[i]  = (const float*)d_in[1 + i];
            proj[i] = (const float*)d_in[5 + i];
        }
    }

    float* out = (float*)d_out;
    const int n_tok = in_sizes[0];   // 16384

    zero_kernel<<<1, 32>>>();
    bucket_kernel<<<(n_tok + 255) / 256, 256>>>(inp, n_tok);

    dim3 grid(D_PROJ / 64, (n_tok + 63) / 64);   // 16 x 256, device-side early exit
    gemm_kernel<1024><<<grid, 256>>>(emb[0], proj[0], out, 0);
    gemm_kernel<256 ><<<grid, 256>>>(emb[1], proj[1], out, 1);
    gemm_kernel<64  ><<<grid, 256>>>(emb[2], proj[2], out, 2);
    gemm_kernel<16  ><<<grid, 256>>>(emb[3], proj[3], out, 3);
}

// round 2
// speedup vs baseline: 1.3588x; 1.3588x over previous
#include <cuda_runtime.h>
#include <cuda_bf16.h>
#include <stdint.h>

#define N_TOKENS_TOTAL 16384
#define D_PROJ 1024
#define EMB_SCALE 32.0f
#define MAX_TILES 264

// ---------------- scratch (no allocations allowed) ----------------
__device__ int g_cnt[4];
__device__ int g_tok[4][N_TOKENS_TOTAL];   // original flat token position
__device__ int g_loc[4][N_TOKENS_TOTAL];   // local embedding row within cluster
__device__ int g_tile_c[MAX_TILES];        // tile row -> cluster
__device__ int g_tile_m0[MAX_TILES];       // tile row -> starting local row
__device__ int g_total_tiles;

__constant__ int c_K[4] = {1024, 256, 64, 16};

// ---------------- helpers ----------------
__device__ __forceinline__ unsigned long long fma2(unsigned long long a,
                                                   unsigned long long b,
                                                   unsigned long long c) {
    unsigned long long d;
    asm("fma.rn.f32x2 %0, %1, %2, %3;" : "=l"(d) : "l"(a), "l"(b), "l"(c));
    return d;
}
__device__ __forceinline__ unsigned long long pack2(float x, float y) {
    unsigned long long r;
    asm("mov.b64 %0, {%1, %2};" : "=l"(r) : "f"(x), "f"(y));
    return r;
}

// ---------------- kernel 1: zero counters ----------------
__global__ void zero_kernel() {
    if (threadIdx.x < 4) g_cnt[threadIdx.x] = 0;
}

// ---------------- kernel 2: bucket tokens by cluster ----------------
__global__ void bucket_kernel(const int* __restrict__ inp, int n) {
    int t = blockIdx.x * blockDim.x + threadIdx.x;
    if (t >= n) return;
    int v = inp[t];
    int c, l;
    if (v < 20000)       { c = 0; l = 0; }
    else if (v < 40000)  { c = 1; l = 20000; }
    else if (v < 200000) { c = 2; l = 40000; }
    else                 { c = 3; l = 200000; }
    int p = atomicAdd(&g_cnt[c], 1);
    g_tok[c][p] = t;
    g_loc[c][p] = v - l;
}

// ---------------- kernel 3: build tile plan ----------------
__global__ void plan_kernel() {
    if (threadIdx.x == 0) {
        int off = 0;
        for (int c = 0; c < 4; c++) {
            int tiles = (g_cnt[c] + 63) >> 6;
            for (int i = 0; i < tiles; i++) {
                g_tile_c[off + i] = c;
                g_tile_m0[off + i] = i << 6;
            }
            off += tiles;
        }
        g_total_tiles = off;
    }
}

// ---------------- kernel 4: fused gathered GEMM + scatter ----------------
// One launch handles all 4 clusters; tile rows are load-balanced by the plan.
// Tile: BM=64 tokens x BN=64 proj cols, BK=16, 256 threads, 4x4 per thread,
// fma.rn.f32x2 packed accumulation, double-buffered smem (1 sync per tile).
__global__ __launch_bounds__(256, 4) void gemm_fused_kernel(
    const float* __restrict__ e0, const float* __restrict__ e1,
    const float* __restrict__ e2, const float* __restrict__ e3,
    const float* __restrict__ p0, const float* __restrict__ p1,
    const float* __restrict__ p2, const float* __restrict__ p3,
    float* __restrict__ out)
{
    constexpr int BM = 64, BN = 64, BK = 16;
    __shared__ float As[2][BK][BM];
    __shared__ float Bs[2][BK][BN];

    const int tile = blockIdx.y;
    if (tile >= g_total_tiles) return;

    const int cluster = g_tile_c[tile];
    const int m0 = g_tile_m0[tile];
    const int cnt = g_cnt[cluster];
    const int K = c_K[cluster];
    const float* emb  = cluster == 0 ? e0 : cluster == 1 ? e1 : cluster == 2 ? e2 : e3;
    const float* proj = cluster == 0 ? p0 : cluster == 1 ? p1 : cluster == 2 ? p2 : p3;

    const int n0 = blockIdx.x * BN;

    const int t  = threadIdx.x;          // 0..255
    const int tx = t & 15;               // 16 col groups of 4
    const int ty = t >> 4;               // 16 row groups of 4
    const int lrow = t >> 2;             // 0..63 : row loaded by this thread
    const int kg   = t & 3;              // 0..3  : 4-float group within BK

    const bool rvalid = (m0 + lrow) < cnt;
    int gl = 0;
    if (rvalid) gl = g_loc[cluster][m0 + lrow];

    const float* aptr = emb  + (size_t)gl * K + kg * 4;
    const float* bptr = proj + (size_t)(n0 + lrow) * K + kg * 4;

    unsigned long long acc2[4][2];
#pragma unroll
    for (int i = 0; i < 4; i++) { acc2[i][0] = 0ull; acc2[i][1] = 0ull; }

    // load + stage first tile
    float4 av = rvalid ? *reinterpret_cast<const float4*>(aptr)
                       : make_float4(0.f, 0.f, 0.f, 0.f);
    float4 bv = *reinterpret_cast<const float4*>(bptr);

    int s = 0;
    As[s][kg * 4 + 0][lrow] = av.x;
    As[s][kg * 4 + 1][lrow] = av.y;
    As[s][kg * 4 + 2][lrow] = av.z;
    As[s][kg * 4 + 3][lrow] = av.w;
    Bs[s][kg * 4 + 0][lrow] = bv.x;
    Bs[s][kg * 4 + 1][lrow] = bv.y;
    Bs[s][kg * 4 + 2][lrow] = bv.z;
    Bs[s][kg * 4 + 3][lrow] = bv.w;
    __syncthreads();

    for (int k0 = 0; k0 < K; k0 += BK) {
        const bool more = (k0 + BK) < K;
        // prefetch next tile into regs (overlaps compute)
        if (more) {
            av = rvalid ? *reinterpret_cast<const float4*>(aptr + k0 + BK)
                        : make_float4(0.f, 0.f, 0.f, 0.f);
            bv = *reinterpret_cast<const float4*>(bptr + k0 + BK);
        }

#pragma unroll
        for (int kk = 0; kk < BK; kk++) {
            const ulonglong2 b2 =
                *reinterpret_cast<const ulonglong2*>(&Bs[s][kk][tx * 4]);
            const float4 a =
                *reinterpret_cast<const float4*>(&As[s][kk][ty * 4]);
            unsigned long long aa;
            aa = pack2(a.x, a.x);
            acc2[0][0] = fma2(aa, b2.x, acc2[0][0]);
            acc2[0][1] = fma2(aa, b2.y, acc2[0][1]);
            aa = pack2(a.y, a.y);
            acc2[1][0] = fma2(aa, b2.x, acc2[1][0]);
            acc2[1][1] = fma2(aa, b2.y, acc2[1][1]);
            aa = pack2(a.z, a.z);
            acc2[2][0] = fma2(aa, b2.x, acc2[2][0]);
            acc2[2][1] = fma2(aa, b2.y, acc2[2][1]);
            aa = pack2(a.w, a.w);
            acc2[3][0] = fma2(aa, b2.x, acc2[3][0]);
            acc2[3][1] = fma2(aa, b2.y, acc2[3][1]);
        }

        if (more) {
            // stage next tile into the other buffer, single barrier
            const int s2 = s ^ 1;
            As[s2][kg * 4 + 0][lrow] = av.x;
            As[s2][kg * 4 + 1][lrow] = av.y;
            As[s2][kg * 4 + 2][lrow] = av.z;
            As[s2][kg * 4 + 3][lrow] = av.w;
            Bs[s2][kg * 4 + 0][lrow] = bv.x;
            Bs[s2][kg * 4 + 1][lrow] = bv.y;
            Bs[s2][kg * 4 + 2][lrow] = bv.z;
            Bs[s2][kg * 4 + 3][lrow] = bv.w;
            __syncthreads();
            s = s2;
        }
    }

    // scatter-store with scale
#pragma unroll
    for (int i = 0; i < 4; i++) {
        int r = m0 + ty * 4 + i;
        if (r < cnt) {
            int row = g_tok[cluster][r];
            float2 q0 = *reinterpret_cast<float2*>(&acc2[i][0]);
            float2 q1 = *reinterpret_cast<float2*>(&acc2[i][1]);
            float4 v = make_float4(q0.x * EMB_SCALE, q0.y * EMB_SCALE,
                                   q1.x * EMB_SCALE, q1.y * EMB_SCALE);
            *reinterpret_cast<float4*>(out + (size_t)row * D_PROJ + n0 + tx * 4) = v;
        }
    }
}

// ---------------- launch ----------------
extern "C" void kernel_launch(void* const* d_in, const int* in_sizes, int n_in,
                              void* d_out, int out_size) {
    const int* inp = (const int*)d_in[0];
    const float* emb[4];
    const float* proj[4];

    if (n_in >= 9 && in_sizes[2] == 1024 * 1024) {
        for (int i = 0; i < 4; i++) {
            emb[i]  = (const float*)d_in[1 + 2 * i];
            proj[i] = (const float*)d_in[2 + 2 * i];
        }
    } else {
        for (int i = 0; i < 4; i++) {
            emb[i]  = (const float*)d_in[1 + i];
            proj[i] = (const float*)d_in[5 + i];
        }
    }

    float* out = (float*)d_out;
    const int n_tok = in_sizes[0];   // 16384

    zero_kernel<<<1, 32>>>();
    bucket_kernel<<<(n_tok + 255) / 256, 256>>>(inp, n_tok);
    plan_kernel<<<1, 32>>>();

    // max tile rows = sum ceil(cnt_c/64) <= 256 + 3
    dim3 grid(D_PROJ / 64, 260);
    gemm_fused_kernel<<<grid, 256>>>(emb[0], emb[1], emb[2], emb[3],
                                     proj[0], proj[1], proj[2], proj[3],
                                     out);
}

// round 4
// speedup vs baseline: 1.8631x; 1.3711x over previous
#include <cuda_runtime.h>
#include <cuda_bf16.h>
#include <stdint.h>

#define N_TOKENS_TOTAL 16384
#define D_PROJ 1024
#define EMB_SCALE 32.0f
#define MAX_TILES 136      // sum ceil(cnt_c/128) <= 128+3

// ---------------- scratch (static device arrays; no allocations) ----------------
__device__ int g_cnt[4];
__device__ int g_tok[4][N_TOKENS_TOTAL];
__device__ int g_loc[4][N_TOKENS_TOTAL];
__device__ int g_tile_c[MAX_TILES];
__device__ int g_tile_m0[MAX_TILES];
__device__ int g_total_tiles;

// bf16 hi/lo split scratch (compacted by bucket order)
#define A_ELEMS (16384u * 1360u)
#define B_ELEMS (1024u * 1360u)
__device__ __nv_bfloat16 g_ahi[A_ELEMS];
__device__ __nv_bfloat16 g_alo[A_ELEMS];
__device__ __nv_bfloat16 g_bhi[B_ELEMS];
__device__ __nv_bfloat16 g_blo[B_ELEMS];

__constant__ int c_K[4]    = {1024, 256, 64, 16};
__constant__ int c_logK[4] = {10, 8, 6, 4};
__constant__ unsigned c_AOFF[4] = {0u, 16384u*1024u, 16384u*1280u, 16384u*1344u};
__constant__ unsigned c_BOFF[4] = {0u, 1024u*1024u, 1024u*1280u, 1024u*1344u};

// ---------------- helpers ----------------
__device__ __forceinline__ uint32_t smem_u32(const void* p) {
    uint32_t a;
    asm("{ .reg .u64 t; cvta.to.shared.u64 t, %1; cvt.u32.u64 %0, t; }" : "=r"(a) : "l"(p));
    return a;
}
__device__ __forceinline__ void ldsm4(uint32_t* r, uint32_t addr) {
    asm volatile("ldmatrix.sync.aligned.m8n8.x4.shared.b16 {%0,%1,%2,%3}, [%4];"
                 : "=r"(r[0]), "=r"(r[1]), "=r"(r[2]), "=r"(r[3]) : "r"(addr));
}
__device__ __forceinline__ void mma_bf16(float* c, const uint32_t* a,
                                         uint32_t b0, uint32_t b1) {
    asm volatile(
        "mma.sync.aligned.m16n8k16.row.col.f32.bf16.bf16.f32 "
        "{%0,%1,%2,%3}, {%4,%5,%6,%7}, {%8,%9}, {%0,%1,%2,%3};"
        : "+f"(c[0]), "+f"(c[1]), "+f"(c[2]), "+f"(c[3])
        : "r"(a[0]), "r"(a[1]), "r"(a[2]), "r"(a[3]), "r"(b0), "r"(b1));
}
// swizzled smem byte address: rows of 128B, XOR bank-swizzle on 16B granules
__device__ __forceinline__ uint32_t swz(uint32_t base, int row, int kbyte) {
    return base + (((uint32_t)(row * 128 + kbyte)) ^ (uint32_t)((row & 7) << 4));
}
// hi/lo split of float2 into two packed bf16x2
__device__ __forceinline__ void split2(float2 f, uint32_t& hi, uint32_t& lo) {
    __nv_bfloat162 h = __float22bfloat162_rn(f);
    float2 hf = __bfloat1622float2(h);
    float2 r = make_float2(f.x - hf.x, f.y - hf.y);
    __nv_bfloat162 l = __float22bfloat162_rn(r);
    hi = *reinterpret_cast<uint32_t*>(&h);
    lo = *reinterpret_cast<uint32_t*>(&l);
}

// ---------------- kernel 1: zero ----------------
__global__ void zero_kernel() {
    if (threadIdx.x < 4) g_cnt[threadIdx.x] = 0;
}

// ---------------- kernel 2: bucket ----------------
__global__ void bucket_kernel(const int* __restrict__ inp, int n) {
    int t = blockIdx.x * blockDim.x + threadIdx.x;
    if (t >= n) return;
    int v = inp[t];
    int c, l;
    if (v < 20000)       { c = 0; l = 0; }
    else if (v < 40000)  { c = 1; l = 20000; }
    else if (v < 200000) { c = 2; l = 40000; }
    else                 { c = 3; l = 200000; }
    int p = atomicAdd(&g_cnt[c], 1);
    g_tok[c][p] = t;
    g_loc[c][p] = v - l;
}

// ---------------- kernel 3: tile plan (BM=128) ----------------
__global__ void plan_kernel() {
    if (threadIdx.x == 0) {
        int off = 0;
        for (int c = 0; c < 4; c++) {
            int tiles = (g_cnt[c] + 127) >> 7;
            for (int i = 0; i < tiles; i++) {
                g_tile_c[off + i] = c;
                g_tile_m0[off + i] = i << 7;
            }
            off += tiles;
        }
        g_total_tiles = off;
    }
}

// ---------------- kernel 4: proj -> bf16 hi/lo ----------------
__global__ void bconv_kernel(const float* __restrict__ p0, const float* __restrict__ p1,
                             const float* __restrict__ p2, const float* __restrict__ p3) {
    int c = blockIdx.y;
    const float* proj = c == 0 ? p0 : c == 1 ? p1 : c == 2 ? p2 : p3;
    int K = c_K[c];
    unsigned base = c_BOFF[c];
    unsigned total = (unsigned)(1024 * K / 2);
    unsigned stride = gridDim.x * blockDim.x;
    for (unsigned p = blockIdx.x * blockDim.x + threadIdx.x; p < total; p += stride) {
        unsigned e = p * 2;
        float2 f = *reinterpret_cast<const float2*>(proj + e);
        uint32_t hi, lo;
        split2(f, hi, lo);
        *reinterpret_cast<uint32_t*>(g_bhi + base + e) = hi;
        *reinterpret_cast<uint32_t*>(g_blo + base + e) = lo;
    }
}

// ---------------- kernel 5: gathered emb rows -> bf16 hi/lo ----------------
__global__ void aconv_kernel(const float* __restrict__ e0, const float* __restrict__ e1,
                             const float* __restrict__ e2, const float* __restrict__ e3) {
    int c = blockIdx.y;
    const float* emb = c == 0 ? e0 : c == 1 ? e1 : c == 2 ? e2 : e3;
    int K = c_K[c], lk = c_logK[c];
    int cnt = g_cnt[c];
    unsigned base = c_AOFF[c];
    unsigned total = (unsigned)(((long)cnt * K) >> 1);
    unsigned stride = gridDim.x * blockDim.x;
    for (unsigned p = blockIdx.x * blockDim.x + threadIdx.x; p < total; p += stride) {
        unsigned e = p * 2;
        int r = (int)(e >> lk);
        int k = (int)(e & (unsigned)(K - 1));
        int gl = g_loc[c][r];
        float2 f = *reinterpret_cast<const float2*>(emb + (size_t)gl * K + k);
        uint32_t hi, lo;
        split2(f, hi, lo);
        unsigned o = base + (unsigned)r * (unsigned)K + (unsigned)k;
        *reinterpret_cast<uint32_t*>(g_ahi + o) = hi;
        *reinterpret_cast<uint32_t*>(g_alo + o) = lo;
    }
}

// ---------------- kernel 6: fused HMMA GEMM + scatter ----------------
// block = 256 thr = 8 warps (4 M x 2 N); tile 128x128, BK=64.
// smem: Ahi[128][64] Alo Bhi Blo bf16, 16KB each = 64KB, XOR-swizzled.
#define OFF_AHI 0
#define OFF_ALO 16384
#define OFF_BHI 32768
#define OFF_BLO 49152
#define SMEM_BYTES 65536

__global__ __launch_bounds__(256, 2) void gemm_mma_kernel(float* __restrict__ out) {
    extern __shared__ char smem[];
    const uint32_t sb = smem_u32(smem);

    const int tile = blockIdx.y;
    if (tile >= g_total_tiles) return;

    const int cluster = g_tile_c[tile];
    const int m0 = g_tile_m0[tile];
    const int cnt = g_cnt[cluster];
    const int K = c_K[cluster];
    const int n0 = blockIdx.x * 128;

    const int tid  = threadIdx.x;
    const int lane = tid & 31;
    const int wid  = tid >> 5;
    const int mwarp = (wid & 3) * 32;     // warp M offset within tile
    const int nwarp = (wid >> 2) * 64;    // warp N offset within tile

    const __nv_bfloat16* ahi = g_ahi + c_AOFF[cluster] + (size_t)m0 * K;
    const __nv_bfloat16* alo = g_alo + c_AOFF[cluster] + (size_t)m0 * K;
    const __nv_bfloat16* bhi = g_bhi + c_BOFF[cluster] + (size_t)n0 * K;
    const __nv_bfloat16* blo = g_blo + c_BOFF[cluster] + (size_t)n0 * K;

    float acc[2][8][4] = {};

    for (int k0 = 0; k0 < K; k0 += 64) {
        const int kc  = (K - k0) < 64 ? (K - k0) : 64;  // 16 or 64
        const int nch = kc >> 3;                        // 16B granules per row

        // cooperative load scratch -> swizzled smem (zero-pad invalid A rows)
        const int nchunks = 128 * nch;
        for (int ci = tid; ci < nchunks; ci += 256) {
            const int r = ci / nch;
            const int j = ci - r * nch;
            const uint32_t sw = (uint32_t)(r * 128 + j * 16) ^ (uint32_t)((r & 7) << 4);
            const size_t src = (size_t)r * K + k0 + j * 8;
            uint4 vh, vl;
            if (m0 + r < cnt) {
                vh = *reinterpret_cast<const uint4*>(ahi + src);
                vl = *reinterpret_cast<const uint4*>(alo + src);
            } else {
                vh = make_uint4(0, 0, 0, 0);
                vl = vh;
            }
            *reinterpret_cast<uint4*>(smem + OFF_AHI + sw) = vh;
            *reinterpret_cast<uint4*>(smem + OFF_ALO + sw) = vl;
            *reinterpret_cast<uint4*>(smem + OFF_BHI + sw) = *reinterpret_cast<const uint4*>(bhi + src);
            *reinterpret_cast<uint4*>(smem + OFF_BLO + sw) = *reinterpret_cast<const uint4*>(blo + src);
        }
        __syncthreads();

        const int ksteps = kc >> 4;      // 1 or 4
        for (int ks = 0; ks < ksteps; ks++) {
            // A fragments: 2 m16 tiles, hi+lo (ldmatrix x4 each)
            uint32_t ah[2][4], al[2][4];
            const int arow = lane & 15;
            const int akb  = ks * 32 + (lane >> 4) * 16;
#pragma unroll
            for (int mt = 0; mt < 2; mt++) {
                const int row = mwarp + mt * 16 + arow;
                ldsm4(ah[mt], swz(sb + OFF_AHI, row, akb));
                ldsm4(al[mt], swz(sb + OFF_ALO, row, akb));
            }
            // B fragments: 8 n8 tiles in 4 x4-loads each for hi and lo
            const int broff = (lane & 7) + ((lane >> 4) << 3);
            const int bkb   = ks * 32 + ((lane >> 3) & 1) * 16;
#pragma unroll
            for (int ng = 0; ng < 4; ng++) {
                uint32_t bh[4], bl[4];
                const int row = nwarp + ng * 16 + broff;
                ldsm4(bh, swz(sb + OFF_BHI, row, bkb));
                ldsm4(bl, swz(sb + OFF_BLO, row, bkb));
#pragma unroll
                for (int mt = 0; mt < 2; mt++) {
                    mma_bf16(acc[mt][2 * ng + 0], ah[mt], bh[0], bh[1]);
                    mma_bf16(acc[mt][2 * ng + 0], ah[mt], bl[0], bl[1]);
                    mma_bf16(acc[mt][2 * ng + 0], al[mt], bh[0], bh[1]);
                    mma_bf16(acc[mt][2 * ng + 1], ah[mt], bh[2], bh[3]);
                    mma_bf16(acc[mt][2 * ng + 1], ah[mt], bl[2], bl[3]);
                    mma_bf16(acc[mt][2 * ng + 1], al[mt], bh[2], bh[3]);
                }
            }
        }
        __syncthreads();
    }

    // epilogue: scale + scatter (fragment rows l/4 and l/4+8)
#pragma unroll
    for (int mt = 0; mt < 2; mt++) {
        const int r0 = m0 + mwarp + mt * 16 + (lane >> 2);
        const int r1 = r0 + 8;
        float* p0 = nullptr;
        float* p1 = nullptr;
        if (r0 < cnt) p0 = out + (size_t)g_tok[cluster][r0] * D_PROJ + n0 + nwarp + (lane & 3) * 2;
        if (r1 < cnt) p1 = out + (size_t)g_tok[cluster][r1] * D_PROJ + n0 + nwarp + (lane & 3) * 2;
#pragma unroll
        for (int nt = 0; nt < 8; nt++) {
            if (p0) *reinterpret_cast<float2*>(p0 + nt * 8) =
                make_float2(acc[mt][nt][0] * EMB_SCALE, acc[mt][nt][1] * EMB_SCALE);
            if (p1) *reinterpret_cast<float2*>(p1 + nt * 8) =
                make_float2(acc[mt][nt][2] * EMB_SCALE, acc[mt][nt][3] * EMB_SCALE);
        }
    }
}

// ---------------- launch ----------------
extern "C" void kernel_launch(void* const* d_in, const int* in_sizes, int n_in,
                              void* d_out, int out_size) {
    const int* inp = (const int*)d_in[0];
    const float* emb[4];
    const float* proj[4];

    if (n_in >= 9 && in_sizes[2] == 1024 * 1024) {
        for (int i = 0; i < 4; i++) {
            emb[i]  = (const float*)d_in[1 + 2 * i];
            proj[i] = (const float*)d_in[2 + 2 * i];
        }
    } else {
        for (int i = 0; i < 4; i++) {
            emb[i]  = (const float*)d_in[1 + i];
            proj[i] = (const float*)d_in[5 + i];
        }
    }

    float* out = (float*)d_out;
    const int n_tok = in_sizes[0];   // 16384

    cudaFuncSetAttribute(gemm_mma_kernel,
                         cudaFuncAttributeMaxDynamicSharedMemorySize, SMEM_BYTES);

    zero_kernel<<<1, 32>>>();
    bucket_kernel<<<(n_tok + 255) / 256, 256>>>(inp, n_tok);
    plan_kernel<<<1, 32>>>();
    bconv_kernel<<<dim3(64, 4), 256>>>(proj[0], proj[1], proj[2], proj[3]);
    aconv_kernel<<<dim3(256, 4), 256>>>(emb[0], emb[1], emb[2], emb[3]);

    dim3 grid(D_PROJ / 128, MAX_TILES);   // 8 x 136, device-side early exit
    gemm_mma_kernel<<<grid, 256, SMEM_BYTES>>>(out);
}

// round 5
// speedup vs baseline: 2.0000x; 1.0735x over previous
#include <cuda_runtime.h>
#include <cuda_bf16.h>
#include <stdint.h>

#define N_TOKENS_TOTAL 16384
#define D_PROJ 1024
#define EMB_SCALE 32.0f
#define MAX_TILES 136      // sum ceil(cnt_c/128) <= 128+3

// ---------------- scratch (static device arrays; no allocations) ----------------
__device__ int g_cnt[4];
__device__ int g_tok[4][N_TOKENS_TOTAL];
__device__ int g_loc[4][N_TOKENS_TOTAL];
__device__ int g_tile_c[MAX_TILES];
__device__ int g_tile_m0[MAX_TILES];
__device__ int g_total_tiles;

__constant__ int c_K[4] = {1024, 256, 64, 16};

// ---------------- helpers ----------------
__device__ __forceinline__ uint32_t smem_u32(const void* p) {
    uint32_t a;
    asm("{ .reg .u64 t; cvta.to.shared.u64 t, %1; cvt.u32.u64 %0, t; }" : "=r"(a) : "l"(p));
    return a;
}
__device__ __forceinline__ void ldsm4(uint32_t* r, uint32_t addr) {
    asm volatile("ldmatrix.sync.aligned.m8n8.x4.shared.b16 {%0,%1,%2,%3}, [%4];"
                 : "=r"(r[0]), "=r"(r[1]), "=r"(r[2]), "=r"(r[3]) : "r"(addr));
}
__device__ __forceinline__ void mma_bf16(float* c, const uint32_t* a,
                                         uint32_t b0, uint32_t b1) {
    asm volatile(
        "mma.sync.aligned.m16n8k16.row.col.f32.bf16.bf16.f32 "
        "{%0,%1,%2,%3}, {%4,%5,%6,%7}, {%8,%9}, {%0,%1,%2,%3};"
        : "+f"(c[0]), "+f"(c[1]), "+f"(c[2]), "+f"(c[3])
        : "r"(a[0]), "r"(a[1]), "r"(a[2]), "r"(a[3]), "r"(b0), "r"(b1));
}
// swizzled smem byte address: rows of 128B, XOR bank-swizzle on 16B granules
__device__ __forceinline__ uint32_t swz(uint32_t base, int row, int kbyte) {
    return base + (((uint32_t)(row * 128 + kbyte)) ^ (uint32_t)((row & 7) << 4));
}
// hi/lo split: float2 -> packed bf16x2 hi + lo
__device__ __forceinline__ void split2(float2 f, uint32_t& hi, uint32_t& lo) {
    __nv_bfloat162 h = __float22bfloat162_rn(f);
    float2 hf = __bfloat1622float2(h);
    float2 r = make_float2(f.x - hf.x, f.y - hf.y);
    __nv_bfloat162 l = __float22bfloat162_rn(r);
    hi = *reinterpret_cast<uint32_t*>(&h);
    lo = *reinterpret_cast<uint32_t*>(&l);
}
// 8 fp32 -> 8 bf16 hi (uint4) + 8 bf16 lo (uint4)
__device__ __forceinline__ void split8(float4 f0, float4 f1, uint4& hi, uint4& lo) {
    split2(make_float2(f0.x, f0.y), hi.x, lo.x);
    split2(make_float2(f0.z, f0.w), hi.y, lo.y);
    split2(make_float2(f1.x, f1.y), hi.z, lo.z);
    split2(make_float2(f1.z, f1.w), hi.w, lo.w);
}

// ---------------- kernel 1: zero ----------------
__global__ void zero_kernel() {
    if (threadIdx.x < 4) g_cnt[threadIdx.x] = 0;
}

// ---------------- kernel 2: bucket ----------------
__global__ void bucket_kernel(const int* __restrict__ inp, int n) {
    int t = blockIdx.x * blockDim.x + threadIdx.x;
    if (t >= n) return;
    int v = inp[t];
    int c, l;
    if (v < 20000)       { c = 0; l = 0; }
    else if (v < 40000)  { c = 1; l = 20000; }
    else if (v < 200000) { c = 2; l = 40000; }
    else                 { c = 3; l = 200000; }
    int p = atomicAdd(&g_cnt[c], 1);
    g_tok[c][p] = t;
    g_loc[c][p] = v - l;
}

// ---------------- kernel 3: tile plan (BM=128), parallel ----------------
__global__ void plan_kernel() {
    __shared__ int offs[5];
    if (threadIdx.x == 0) {
        offs[0] = 0;
        for (int c = 0; c < 4; c++) offs[c + 1] = offs[c] + ((g_cnt[c] + 127) >> 7);
        g_total_tiles = offs[4];
    }
    __syncthreads();
    const int total = offs[4];
    for (int i = threadIdx.x; i < total; i += blockDim.x) {
        int c = 0;
        while (i >= offs[c + 1]) c++;
        g_tile_c[i] = c;
        g_tile_m0[i] = (i - offs[c]) << 7;
    }
}

// ---------------- kernel 4: fused gather + split + HMMA GEMM + scatter ----------------
// block = 256 thr = 8 warps (4 M x 2 N); tile 128x128, BK=64.
// smem: Ahi/Alo/Bhi/Blo [128][64] bf16 XOR-swizzled, 16KB each = 64KB.
#define OFF_AHI 0
#define OFF_ALO 16384
#define OFF_BHI 32768
#define OFF_BLO 49152
#define SMEM_BYTES 65536

__global__ __launch_bounds__(256, 2) void gemm_mma_kernel(
    const float* __restrict__ e0, const float* __restrict__ e1,
    const float* __restrict__ e2, const float* __restrict__ e3,
    const float* __restrict__ p0, const float* __restrict__ p1,
    const float* __restrict__ p2, const float* __restrict__ p3,
    float* __restrict__ out)
{
    extern __shared__ char smem[];
    const uint32_t sb = smem_u32(smem);
    __shared__ int s_loc[128];

    const int tile = blockIdx.y;
    if (tile >= g_total_tiles) return;

    const int cluster = g_tile_c[tile];
    const int m0 = g_tile_m0[tile];
    const int cnt = g_cnt[cluster];
    const int K = c_K[cluster];
    const int n0 = blockIdx.x * 128;
    const float* emb  = cluster == 0 ? e0 : cluster == 1 ? e1 : cluster == 2 ? e2 : e3;
    const float* proj = cluster == 0 ? p0 : cluster == 1 ? p1 : cluster == 2 ? p2 : p3;

    const int tid  = threadIdx.x;
    const int lane = tid & 31;
    const int wid  = tid >> 5;
    const int mwarp = (wid & 3) * 32;     // warp M offset
    const int nwarp = (wid >> 2) * 64;    // warp N offset

    // preload gathered row indices (reused across all K chunks)
    for (int i = tid; i < 128; i += 256) {
        const int r = m0 + i;
        s_loc[i] = (r < cnt) ? g_loc[cluster][r] : -1;
    }
    __syncthreads();

    float acc[2][8][4] = {};

    for (int k0 = 0; k0 < K; k0 += 64) {
        const int kc  = (K - k0) < 64 ? (K - k0) : 64;  // 16 or 64
        const int lgn = (kc == 64) ? 3 : 1;             // log2 granules per row
        const int nch = 1 << lgn;

        // stage: gather fp32, split to bf16 hi/lo, store swizzled smem
        const int tot = 128 * nch;
        for (int ci = tid; ci < tot; ci += 256) {
            const int r = ci >> lgn;
            const int j = ci & (nch - 1);
            const uint32_t sw = (uint32_t)(r * 128 + j * 16) ^ (uint32_t)((r & 7) << 4);
            // A (gathered, may be invalid row)
            const int gl = s_loc[r];
            uint4 ahiv, alov;
            if (gl >= 0) {
                const float* s = emb + (size_t)gl * K + k0 + j * 8;
                split8(*reinterpret_cast<const float4*>(s),
                       *reinterpret_cast<const float4*>(s + 4), ahiv, alov);
            } else {
                ahiv = make_uint4(0, 0, 0, 0);
                alov = ahiv;
            }
            *reinterpret_cast<uint4*>(smem + OFF_AHI + sw) = ahiv;
            *reinterpret_cast<uint4*>(smem + OFF_ALO + sw) = alov;
            // B (dense)
            const float* sB = proj + (size_t)(n0 + r) * K + k0 + j * 8;
            uint4 bhiv, blov;
            split8(*reinterpret_cast<const float4*>(sB),
                   *reinterpret_cast<const float4*>(sB + 4), bhiv, blov);
            *reinterpret_cast<uint4*>(smem + OFF_BHI + sw) = bhiv;
            *reinterpret_cast<uint4*>(smem + OFF_BLO + sw) = blov;
        }
        __syncthreads();

        const int ksteps = kc >> 4;      // 1 or 4
        for (int ks = 0; ks < ksteps; ks++) {
            uint32_t ah[2][4], al[2][4];
            const int arow = lane & 15;
            const int akb  = ks * 32 + (lane >> 4) * 16;
#pragma unroll
            for (int mt = 0; mt < 2; mt++) {
                const int row = mwarp + mt * 16 + arow;
                ldsm4(ah[mt], swz(sb + OFF_AHI, row, akb));
                ldsm4(al[mt], swz(sb + OFF_ALO, row, akb));
            }
            const int broff = (lane & 7) + ((lane >> 4) << 3);
            const int bkb   = ks * 32 + ((lane >> 3) & 1) * 16;
#pragma unroll
            for (int ng = 0; ng < 4; ng++) {
                uint32_t bh[4], bl[4];
                const int row = nwarp + ng * 16 + broff;
                ldsm4(bh, swz(sb + OFF_BHI, row, bkb));
                ldsm4(bl, swz(sb + OFF_BLO, row, bkb));
#pragma unroll
                for (int mt = 0; mt < 2; mt++) {
                    mma_bf16(acc[mt][2 * ng + 0], ah[mt], bh[0], bh[1]);
                    mma_bf16(acc[mt][2 * ng + 0], ah[mt], bl[0], bl[1]);
                    mma_bf16(acc[mt][2 * ng + 0], al[mt], bh[0], bh[1]);
                    mma_bf16(acc[mt][2 * ng + 1], ah[mt], bh[2], bh[3]);
                    mma_bf16(acc[mt][2 * ng + 1], ah[mt], bl[2], bl[3]);
                    mma_bf16(acc[mt][2 * ng + 1], al[mt], bh[2], bh[3]);
                }
            }
        }
        __syncthreads();
    }

    // epilogue: scale + scatter
#pragma unroll
    for (int mt = 0; mt < 2; mt++) {
        const int r0 = m0 + mwarp + mt * 16 + (lane >> 2);
        const int r1 = r0 + 8;
        float* q0 = nullptr;
        float* q1 = nullptr;
        if (r0 < cnt) q0 = out + (size_t)g_tok[cluster][r0] * D_PROJ + n0 + nwarp + (lane & 3) * 2;
        if (r1 < cnt) q1 = out + (size_t)g_tok[cluster][r1] * D_PROJ + n0 + nwarp + (lane & 3) * 2;
#pragma unroll
        for (int nt = 0; nt < 8; nt++) {
            if (q0) *reinterpret_cast<float2*>(q0 + nt * 8) =
                make_float2(acc[mt][nt][0] * EMB_SCALE, acc[mt][nt][1] * EMB_SCALE);
            if (q1) *reinterpret_cast<float2*>(q1 + nt * 8) =
                make_float2(acc[mt][nt][2] * EMB_SCALE, acc[mt][nt][3] * EMB_SCALE);
        }
    }
}

// ---------------- launch ----------------
extern "C" void kernel_launch(void* const* d_in, const int* in_sizes, int n_in,
                              void* d_out, int out_size) {
    const int* inp = (const int*)d_in[0];
    const float* emb[4];
    const float* proj[4];

    if (n_in >= 9 && in_sizes[2] == 1024 * 1024) {
        for (int i = 0; i < 4; i++) {
            emb[i]  = (const float*)d_in[1 + 2 * i];
            proj[i] = (const float*)d_in[2 + 2 * i];
        }
    } else {
        for (int i = 0; i < 4; i++) {
            emb[i]  = (const float*)d_in[1 + i];
            proj[i] = (const float*)d_in[5 + i];
        }
    }

    float* out = (float*)d_out;
    const int n_tok = in_sizes[0];   // 16384

    cudaFuncSetAttribute(gemm_mma_kernel,
                         cudaFuncAttributeMaxDynamicSharedMemorySize, SMEM_BYTES);

    zero_kernel<<<1, 32>>>();
    bucket_kernel<<<(n_tok + 255) / 256, 256>>>(inp, n_tok);
    plan_kernel<<<1, 128>>>();

    dim3 grid(D_PROJ / 128, MAX_TILES);   // 8 x 136, device-side early exit
    gemm_mma_kernel<<<grid, 256, SMEM_BYTES>>>(emb[0], emb[1], emb[2], emb[3],
                                               proj[0], proj[1], proj[2], proj[3],
                                               out);
}